// round 16
// baseline (speedup 1.0000x reference)
#include <cuda_runtime.h>
#include <cuda_bf16.h>

// MultiHeadSpMM: out[r, h*D+d] = sum_{e: row[e]==r} attention[e,h] * h[col[e],h,d]
// N=100000, E=1600000, H=4, D=8 (H*D == 32). row[] is sorted.
//
// R16: R15 hot loop (measured best) + DYNAMIC row assignment.
//   Static group->row mapping pays E[max of 4 Poisson(16)]/16 ~= 1.35x
//   serialization inflation per warp. Instead: each 256-thread block owns a
//   pool of 64 consecutive rows + a smem counter. Each 8-lane group pulls
//   rows dynamically (leader atomicAdd on smem, broadcast via group-masked
//   shfl -- group lanes are always convergent: their control flow depends
//   only on group-shared values). Greedy scheduling -> ~1.05x inflation.
//   Inner per-row loop identical to R15.

#define MAX_NODES (1 << 21)
#define POOL_ROWS 64            // rows per block
#define THREADS   256           // 32 groups of 8 lanes

__device__ int g_row_ptr[MAX_NODES + 1];

__global__ void build_row_ptr_kernel(const int* __restrict__ row, int E, int N) {
    int e = blockIdx.x * blockDim.x + threadIdx.x;
    if (e >= E) return;
    int r = row[e];
    if (r < 0) r = 0;
    if (r >= N) r = N - 1;
    int prev;
    if (e == 0) {
        prev = -1;
    } else {
        prev = row[e - 1];
        if (prev < 0) prev = 0;
        if (prev >= N) prev = N - 1;
    }
    for (int i = prev + 1; i <= r; ++i) g_row_ptr[i] = e;
    if (e == E - 1) {
        for (int i = r + 1; i <= N; ++i) g_row_ptr[i] = E;
    }
}

__global__ __launch_bounds__(THREADS) void spmm_pool_kernel(
    const int* __restrict__ col,
    const float* __restrict__ att,   // (E, 4)
    const float* __restrict__ hfeat, // (N, 32)
    float* __restrict__ out,         // (N, 32)
    int N)
{
    __shared__ int s_ctr;

    const int tid  = threadIdx.x;
    const int lane = tid & 31;
    const int wg   = lane >> 3;            // group index within warp (0..3)
    const int q    = lane & 7;             // feature quarter
    const int hd   = q >> 1;               // head for this quarter
    const int gid  = tid >> 3;             // group index within block (0..31)
    const unsigned gmask = 0xFFu << (wg * 8);
    const int gleader = wg * 8;            // absolute lane of group leader

    const int base = blockIdx.x * POOL_ROWS;
    const int nmax = N - 1;

    if (tid == 0) s_ctr = THREADS / 8;     // first 32 pulls are static
    __syncthreads();

    int idx = gid;                          // static first row for each group
    while (idx < POOL_ROWS) {
        const int r = base + idx;
        if (r < N) {
            const int beg = g_row_ptr[r];
            const int end = g_row_ptr[r + 1];

            float4 acc = make_float4(0.f, 0.f, 0.f, 0.f);

            int e = beg;
            for (; e + 3 < end; e += 4) {
                int c0 = __ldg(&col[e]);
                int c1 = __ldg(&col[e + 1]);
                int c2 = __ldg(&col[e + 2]);
                int c3 = __ldg(&col[e + 3]);

                float a0 = __ldg(&att[(e    ) * 4 + hd]);
                float a1 = __ldg(&att[(e + 1) * 4 + hd]);
                float a2 = __ldg(&att[(e + 2) * 4 + hd]);
                float a3 = __ldg(&att[(e + 3) * 4 + hd]);

                c0 = min(max(c0, 0), nmax);
                c1 = min(max(c1, 0), nmax);
                c2 = min(max(c2, 0), nmax);
                c3 = min(max(c3, 0), nmax);

                float4 h0 = __ldg((const float4*)(hfeat + c0 * 32 + q * 4));
                float4 h1 = __ldg((const float4*)(hfeat + c1 * 32 + q * 4));
                float4 h2 = __ldg((const float4*)(hfeat + c2 * 32 + q * 4));
                float4 h3 = __ldg((const float4*)(hfeat + c3 * 32 + q * 4));

                acc.x = fmaf(a0, h0.x, acc.x);
                acc.y = fmaf(a0, h0.y, acc.y);
                acc.z = fmaf(a0, h0.z, acc.z);
                acc.w = fmaf(a0, h0.w, acc.w);
                acc.x = fmaf(a1, h1.x, acc.x);
                acc.y = fmaf(a1, h1.y, acc.y);
                acc.z = fmaf(a1, h1.z, acc.z);
                acc.w = fmaf(a1, h1.w, acc.w);
                acc.x = fmaf(a2, h2.x, acc.x);
                acc.y = fmaf(a2, h2.y, acc.y);
                acc.z = fmaf(a2, h2.z, acc.z);
                acc.w = fmaf(a2, h2.w, acc.w);
                acc.x = fmaf(a3, h3.x, acc.x);
                acc.y = fmaf(a3, h3.y, acc.y);
                acc.z = fmaf(a3, h3.z, acc.z);
                acc.w = fmaf(a3, h3.w, acc.w);
            }
            for (; e < end; ++e) {
                int c = __ldg(&col[e]);
                c = min(max(c, 0), nmax);
                float a = __ldg(&att[e * 4 + hd]);
                float4 h0 = __ldg((const float4*)(hfeat + c * 32 + q * 4));
                acc.x = fmaf(a, h0.x, acc.x);
                acc.y = fmaf(a, h0.y, acc.y);
                acc.z = fmaf(a, h0.z, acc.z);
                acc.w = fmaf(a, h0.w, acc.w);
            }

            ((float4*)out)[r * 8 + q] = acc;   // zeros for empty rows
        }

        // Pull next row index from the block pool (group-convergent).
        int v = 0;
        if (q == 0) v = atomicAdd(&s_ctr, 1);
        idx = __shfl_sync(gmask, v, gleader);
    }
}

extern "C" void kernel_launch(void* const* d_in, const int* in_sizes, int n_in,
                              void* d_out, int out_size) {
    const int*   row  = (const int*)  d_in[0];
    const int*   col  = (const int*)  d_in[1];
    const float* att  = (const float*)d_in[2];
    const float* hft  = (const float*)d_in[3];
    float*       out  = (float*)      d_out;

    int E = in_sizes[0];
    int N = in_sizes[3] / 32;  // h is (N, 4, 8)

    {
        int threads = 256;
        int blocks = (E + threads - 1) / threads;
        build_row_ptr_kernel<<<blocks, threads>>>(row, E, N);
    }
    {
        int blocks = (N + POOL_ROWS - 1) / POOL_ROWS;
        spmm_pool_kernel<<<blocks, THREADS>>>(col, att, hft, out, N);
    }
}